// round 2
// baseline (speedup 1.0000x reference)
#include <cuda_runtime.h>
#include <math.h>
#include <stdint.h>

// ---------------- problem constants ----------------
#define T_TOK   32768          // B*S tokens
#define D_DIM   1024
#define E_EXP   16
#define I_DIM   2816
#define TWO_I   5632
#define TK_SLOTS 65536         // T * k
#define CAP     5120           // ceil(T*k/E * 1.25)
#define NB      64             // blocks in pos kernel
#define SPB     1024           // slots per pos-block (TK/NB)

// ---------------- scratch (device globals; no allocs) ----------------
__device__ float g_expert_in[(size_t)E_EXP * CAP * D_DIM];   // 336 MB
__device__ float g_h[(size_t)E_EXP * CAP * TWO_I];           // 1.85 GB
__device__ float g_act[(size_t)E_EXP * CAP * I_DIM];         // 922 MB
__device__ float g_eout[(size_t)E_EXP * CAP * D_DIM];        // 336 MB
__device__ int   g_sel[TK_SLOTS];
__device__ float g_comb[TK_SLOTS];
__device__ int   g_poslocal[TK_SLOTS];
__device__ int   g_slot[TK_SLOTS];       // e*CAP+pos if kept, else -1
__device__ int   g_blkCnt[NB][E_EXP];
__device__ int   g_blkOff[NB][E_EXP];
__device__ int   g_cnt[E_EXP];
__device__ float g_sumprobs[E_EXP];
__device__ float g_z2;

// ---------------- stats zeroing ----------------
__global__ void zero_stats_kernel() {
    if (threadIdx.x < E_EXP) g_sumprobs[threadIdx.x] = 0.f;
    if (threadIdx.x == 0)    g_z2 = 0.f;
}

// ---------------- router: logits, softmax stats, top-2, combine ----------------
// one warp per token
__global__ void router_kernel(const float* __restrict__ x,
                              const float* __restrict__ router) {
    __shared__ float s_p[E_EXP];
    __shared__ float s_z2;
    if (threadIdx.x < E_EXP) s_p[threadIdx.x] = 0.f;
    if (threadIdx.x == 0)    s_z2 = 0.f;
    __syncthreads();

    const int gwarp = (blockIdx.x * blockDim.x + threadIdx.x) >> 5;
    const int lane  = threadIdx.x & 31;

    if (gwarp < T_TOK) {
        const float* xr = x + (size_t)gwarp * D_DIM;
        float acc[E_EXP];
        #pragma unroll
        for (int e = 0; e < E_EXP; e++) acc[e] = 0.f;

        for (int i = lane; i < D_DIM; i += 32) {
            float xv = xr[i];
            const float* rr = router + (size_t)i * E_EXP;
            #pragma unroll
            for (int e = 0; e < E_EXP; e++) acc[e] += xv * rr[e];
        }
        #pragma unroll
        for (int off = 16; off; off >>= 1) {
            #pragma unroll
            for (int e = 0; e < E_EXP; e++)
                acc[e] += __shfl_xor_sync(0xffffffffu, acc[e], off);
        }
        // all lanes now hold the 16 logits
        float m = acc[0];
        #pragma unroll
        for (int e = 1; e < E_EXP; e++) m = fmaxf(m, acc[e]);
        float se = 0.f;
        #pragma unroll
        for (int e = 0; e < E_EXP; e++) se += expf(acc[e] - m);
        float z = m + logf(se);

        // top-2 (strict > keeps lowest index on ties, matching lax.top_k)
        int i1 = 0; float l1 = acc[0];
        #pragma unroll
        for (int e = 1; e < E_EXP; e++) if (acc[e] > l1) { l1 = acc[e]; i1 = e; }
        int i2 = -1; float l2 = -1e30f;
        #pragma unroll
        for (int e = 0; e < E_EXP; e++)
            if (e != i1 && acc[e] > l2) { l2 = acc[e]; i2 = e; }

        float q  = expf(l2 - l1);
        float c1 = 1.f / (1.f + q);
        float c2 = q / (1.f + q);

        if (lane == 0) {
            g_sel[2 * gwarp]     = i1;
            g_sel[2 * gwarp + 1] = i2;
            g_comb[2 * gwarp]     = c1;
            g_comb[2 * gwarp + 1] = c2;
            atomicAdd(&s_z2, z * z);
        }
        if (lane < E_EXP) atomicAdd(&s_p[lane], expf(acc[lane] - m) / se);
    }
    __syncthreads();
    if (threadIdx.x < E_EXP) atomicAdd(&g_sumprobs[threadIdx.x], s_p[threadIdx.x]);
    if (threadIdx.x == 0)    atomicAdd(&g_z2, s_z2);
}

// ---------------- ordered per-expert rank within each block of SPB slots ----------------
__global__ void pos_kernel() {
    __shared__ int warpCnt[8][E_EXP];
    __shared__ int running[E_EXP];
    const int tid  = threadIdx.x;
    const int wid  = tid >> 5;
    const int lane = tid & 31;
    if (tid < E_EXP) running[tid] = 0;
    __syncthreads();

    const int base = blockIdx.x * SPB;
    for (int it = 0; it < SPB / 256; it++) {
        const int s = base + it * 256 + tid;
        const int e = g_sel[s];
        unsigned peers = __match_any_sync(0xffffffffu, e);
        const int rank = __popc(peers & ((1u << lane) - 1u));
        if (lane < E_EXP) warpCnt[wid][lane] = 0;
        __syncwarp();
        if (rank == 0) warpCnt[wid][e] = __popc(peers);
        __syncthreads();
        int off = running[e] + rank;
        for (int w = 0; w < wid; w++) off += warpCnt[w][e];
        g_poslocal[s] = off;
        __syncthreads();
        if (tid < E_EXP) {
            int tot = 0;
            #pragma unroll
            for (int w = 0; w < 8; w++) tot += warpCnt[w][tid];
            running[tid] += tot;
        }
        __syncthreads();
    }
    if (tid < E_EXP) g_blkCnt[blockIdx.x][tid] = running[tid];
}

// ---------------- scan block counts -> block offsets + per-expert totals ----------------
__global__ void scan_kernel() {
    const int e = threadIdx.x;
    if (e >= E_EXP) return;
    int run = 0;
    for (int b = 0; b < NB; b++) {
        g_blkOff[b][e] = run;
        run += g_blkCnt[b][e];
    }
    g_cnt[e] = run;  // pre-capacity counts (matches reference expert_counts)
}

// ---------------- scatter kept tokens into expert_in ----------------
// one warp per slot
__global__ void scatter_kernel(const float* __restrict__ x) {
    const int gwarp = (blockIdx.x * blockDim.x + threadIdx.x) >> 5;
    const int lane  = threadIdx.x & 31;
    if (gwarp >= TK_SLOTS) return;
    const int e   = g_sel[gwarp];
    const int pos = g_poslocal[gwarp] + g_blkOff[gwarp / SPB][e];
    int slot = -1;
    if (pos < CAP) {
        slot = e * CAP + pos;
        const float4* src = (const float4*)(x + (size_t)(gwarp >> 1) * D_DIM);
        float4* dst = (float4*)(g_expert_in + (size_t)slot * D_DIM);
        #pragma unroll
        for (int i = 0; i < 8; i++) dst[lane + 32 * i] = src[lane + 32 * i];
    }
    if (lane == 0) g_slot[gwarp] = slot;
}

// ---------------- grouped SGEMM: 128x128x16 tile, 8x8 per thread ----------------
// WHICH==1: A=g_expert_in [CAP,Kdim], B=w_up_gate[e], C=g_h
// WHICH==2: A=g_act      [CAP,Kdim], B=w_down[e],    C=g_eout
template <int Kdim, int Ndim, int WHICH>
__global__ __launch_bounds__(256)
void sgemm_kernel(const float* __restrict__ W) {
    const int e   = blockIdx.z;
    const int cnt = g_cnt[e];
    const int m0  = blockIdx.y * 128;
    if (m0 >= cnt) return;   // rows beyond routed count are never consumed

    const float* __restrict__ Abase = (WHICH == 1) ? g_expert_in : g_act;
    float*       __restrict__ Cbase = (WHICH == 1) ? g_h : g_eout;

    const float* __restrict__ A  = Abase + (size_t)e * CAP * Kdim + (size_t)m0 * Kdim;
    const float* __restrict__ Bm = W + (size_t)e * Kdim * Ndim + blockIdx.x * 128;
    float*       __restrict__ Cc = Cbase + (size_t)e * CAP * Ndim + (size_t)m0 * Ndim
                                   + blockIdx.x * 128;

    __shared__ float As[16][128];
    __shared__ float Bs[16][128];

    const int tid  = threadIdx.x;
    const int tr   = tid >> 4;          // 0..15
    const int tc   = tid & 15;          // 0..15
    const int aRow = tid >> 2;          // 0..63
    const int aCol = (tid & 3) << 2;    // 0,4,8,12
    const int bRow = tid >> 5;          // 0..7
    const int bCol = (tid & 31) << 2;   // 0..124

    float acc[8][8];
    #pragma unroll
    for (int i = 0; i < 8; i++)
        #pragma unroll
        for (int j = 0; j < 8; j++) acc[i][j] = 0.f;

    for (int k0 = 0; k0 < Kdim; k0 += 16) {
        #pragma unroll
        for (int i = 0; i < 2; i++) {
            float4 v = *(const float4*)(A + (size_t)(aRow + 64 * i) * Kdim + k0 + aCol);
            As[aCol + 0][aRow + 64 * i] = v.x;
            As[aCol + 1][aRow + 64 * i] = v.y;
            As[aCol + 2][aRow + 64 * i] = v.z;
            As[aCol + 3][aRow + 64 * i] = v.w;
        }
        #pragma unroll
        for (int i = 0; i < 2; i++) {
            *(float4*)&Bs[bRow + 8 * i][bCol] =
                *(const float4*)(Bm + (size_t)(k0 + bRow + 8 * i) * Ndim + bCol);
        }
        __syncthreads();
        #pragma unroll
        for (int k = 0; k < 16; k++) {
            float rm[8], rn[8];
            *(float4*)&rm[0] = *(const float4*)&As[k][tr * 8];
            *(float4*)&rm[4] = *(const float4*)&As[k][tr * 8 + 4];
            *(float4*)&rn[0] = *(const float4*)&Bs[k][tc * 8];
            *(float4*)&rn[4] = *(const float4*)&Bs[k][tc * 8 + 4];
            #pragma unroll
            for (int i = 0; i < 8; i++)
                #pragma unroll
                for (int j = 0; j < 8; j++)
                    acc[i][j] += rm[i] * rn[j];
        }
        __syncthreads();
    }
    #pragma unroll
    for (int i = 0; i < 8; i++) {
        float* crow = Cc + (size_t)(tr * 8 + i) * Ndim + tc * 8;
        *(float4*)crow       = make_float4(acc[i][0], acc[i][1], acc[i][2], acc[i][3]);
        *(float4*)(crow + 4) = make_float4(acc[i][4], acc[i][5], acc[i][6], acc[i][7]);
    }
}

// ---------------- SiLU(gate)*up, one block per (expert,row) ----------------
__global__ void silu_kernel() {
    const int row = blockIdx.x;            // 0 .. E*CAP-1
    const int e = row / CAP;
    if ((row - e * CAP) >= g_cnt[e]) return;
    const float4* h = (const float4*)(g_h + (size_t)row * TWO_I);
    float4* a = (float4*)(g_act + (size_t)row * I_DIM);
    for (int i = threadIdx.x; i < I_DIM / 4; i += blockDim.x) {
        float4 g = h[i];
        float4 u = h[I_DIM / 4 + i];
        float4 o;
        o.x = g.x / (1.f + expf(-g.x)) * u.x;
        o.y = g.y / (1.f + expf(-g.y)) * u.y;
        o.z = g.z / (1.f + expf(-g.z)) * u.z;
        o.w = g.w / (1.f + expf(-g.w)) * u.w;
        a[i] = o;
    }
}

// ---------------- gather + weighted combine: one warp per token ----------------
__global__ void gather_kernel(float* __restrict__ out) {
    const int t    = (blockIdx.x * blockDim.x + threadIdx.x) >> 5;
    const int lane = threadIdx.x & 31;
    if (t >= T_TOK) return;
    const int s0 = 2 * t, s1 = s0 + 1;
    const int sl0 = g_slot[s0], sl1 = g_slot[s1];
    const float w0 = g_comb[s0], w1 = g_comb[s1];
    const float4* r0 = (sl0 >= 0) ? (const float4*)(g_eout + (size_t)sl0 * D_DIM) : nullptr;
    const float4* r1 = (sl1 >= 0) ? (const float4*)(g_eout + (size_t)sl1 * D_DIM) : nullptr;
    float4* orow = (float4*)(out + (size_t)t * D_DIM);
    #pragma unroll
    for (int ii = 0; ii < 8; ii++) {
        const int i = lane + 32 * ii;
        float4 a = make_float4(0.f, 0.f, 0.f, 0.f);
        if (r0) { float4 v = r0[i]; a.x += w0 * v.x; a.y += w0 * v.y; a.z += w0 * v.z; a.w += w0 * v.w; }
        if (r1) { float4 v = r1[i]; a.x += w1 * v.x; a.y += w1 * v.y; a.z += w1 * v.z; a.w += w1 * v.w; }
        orow[i] = a;
    }
}

// ---------------- final scalars ----------------
__global__ void finalize_kernel(float* __restrict__ out) {
    __shared__ float cnts[E_EXP];
    const size_t base = (size_t)T_TOK * D_DIM;
    if (threadIdx.x < E_EXP) {
        float c = (float)g_cnt[threadIdx.x];
        cnts[threadIdx.x] = c;
        out[base + threadIdx.x] = c;
    }
    __syncthreads();
    if (threadIdx.x == 0) {
        float total = 0.f;
        #pragma unroll
        for (int e = 0; e < E_EXP; e++) total += cnts[e];
        total = fmaxf(total, 1.f);
        float ent = 0.f, lb = 0.f;
        #pragma unroll
        for (int e = 0; e < E_EXP; e++) {
            float f = cnts[e] / total;
            ent -= f * logf(f + 1e-6f);
            lb  += (f * 2.0f) * (g_sumprobs[e] / (float)T_TOK);
        }
        lb *= (float)E_EXP;
        out[base + 16] = ent;
        out[base + 17] = lb;
        out[base + 18] = g_z2 / (float)T_TOK;
    }
}

// ---------------- launch ----------------
extern "C" void kernel_launch(void* const* d_in, const int* in_sizes, int n_in,
                              void* d_out, int out_size) {
    const float* x      = (const float*)d_in[0];
    const float* router = (const float*)d_in[1];
    const float* w_ug   = (const float*)d_in[2];
    const float* w_dn   = (const float*)d_in[3];
    float* out = (float*)d_out;

    zero_stats_kernel<<<1, 32>>>();
    router_kernel<<<T_TOK / 8, 256>>>(x, router);
    pos_kernel<<<NB, 256>>>();
    scan_kernel<<<1, 32>>>();
    scatter_kernel<<<TK_SLOTS / 8, 256>>>(x);
    sgemm_kernel<D_DIM, TWO_I, 1><<<dim3(TWO_I / 128, CAP / 128, E_EXP), 256>>>(w_ug);
    silu_kernel<<<E_EXP * CAP, 256>>>();
    sgemm_kernel<I_DIM, D_DIM, 2><<<dim3(D_DIM / 128, CAP / 128, E_EXP), 256>>>(w_dn);
    gather_kernel<<<T_TOK / 8, 256>>>(out);
    finalize_kernel<<<1, 32>>>(out);
}

// round 4
// speedup vs baseline: 3.0457x; 3.0457x over previous
#include <cuda_runtime.h>
#include <math.h>
#include <stdint.h>

// ---------------- problem constants ----------------
#define T_TOK   32768
#define D_DIM   1024
#define E_EXP   16
#define I_DIM   2816
#define TWO_I   5632
#define TK_SLOTS 65536
#define CAP     5120
#define NB      64
#define SPB     1024

// ---------------- scratch (device globals; no allocs) ----------------
__device__ float g_expert_in[(size_t)E_EXP * CAP * D_DIM];
__device__ float g_h[(size_t)E_EXP * CAP * TWO_I];
__device__ float g_act[(size_t)E_EXP * CAP * I_DIM];
__device__ float g_eout[(size_t)E_EXP * CAP * D_DIM];
__device__ float g_wug_t[(size_t)E_EXP * TWO_I * D_DIM];   // [E][2I][D]
__device__ float g_wdn_t[(size_t)E_EXP * D_DIM * I_DIM];   // [E][D][I]
__device__ int   g_sel[TK_SLOTS];
__device__ float g_comb[TK_SLOTS];
__device__ int   g_poslocal[TK_SLOTS];
__device__ int   g_slot[TK_SLOTS];
__device__ int   g_blkCnt[NB][E_EXP];
__device__ int   g_blkOff[NB][E_EXP];
__device__ int   g_cnt[E_EXP];
__device__ float g_sumprobs[E_EXP];
__device__ float g_z2;

// ---------------- mma helpers (sm_80+ ISA, valid for compute_103) ----------------
__device__ __forceinline__ uint32_t f2tf32(float f) {
    uint32_t r;
    asm("cvt.rna.tf32.f32 %0, %1;" : "=r"(r) : "f"(f));
    return r;
}
__device__ __forceinline__ void mma_tf32(float* c,
                                         uint32_t a0, uint32_t a1, uint32_t a2, uint32_t a3,
                                         uint32_t b0, uint32_t b1) {
    asm volatile("mma.sync.aligned.m16n8k8.row.col.f32.tf32.tf32.f32 "
                 "{%0,%1,%2,%3}, {%4,%5,%6,%7}, {%8,%9}, {%0,%1,%2,%3};"
                 : "+f"(c[0]), "+f"(c[1]), "+f"(c[2]), "+f"(c[3])
                 : "r"(a0), "r"(a1), "r"(a2), "r"(a3), "r"(b0), "r"(b1));
}

// ---------------- stats zeroing ----------------
__global__ void zero_stats_kernel() {
    if (threadIdx.x < E_EXP) g_sumprobs[threadIdx.x] = 0.f;
    if (threadIdx.x == 0)    g_z2 = 0.f;
}

// ---------------- router ----------------
__global__ void router_kernel(const float* __restrict__ x,
                              const float* __restrict__ router) {
    __shared__ float s_p[E_EXP];
    __shared__ float s_z2;
    if (threadIdx.x < E_EXP) s_p[threadIdx.x] = 0.f;
    if (threadIdx.x == 0)    s_z2 = 0.f;
    __syncthreads();

    const int gwarp = (blockIdx.x * blockDim.x + threadIdx.x) >> 5;
    const int lane  = threadIdx.x & 31;

    if (gwarp < T_TOK) {
        const float* xr = x + (size_t)gwarp * D_DIM;
        float acc[E_EXP];
        #pragma unroll
        for (int e = 0; e < E_EXP; e++) acc[e] = 0.f;
        for (int i = lane; i < D_DIM; i += 32) {
            float xv = xr[i];
            const float* rr = router + (size_t)i * E_EXP;
            #pragma unroll
            for (int e = 0; e < E_EXP; e++) acc[e] += xv * rr[e];
        }
        #pragma unroll
        for (int off = 16; off; off >>= 1) {
            #pragma unroll
            for (int e = 0; e < E_EXP; e++)
                acc[e] += __shfl_xor_sync(0xffffffffu, acc[e], off);
        }
        float m = acc[0];
        #pragma unroll
        for (int e = 1; e < E_EXP; e++) m = fmaxf(m, acc[e]);
        float se = 0.f;
        #pragma unroll
        for (int e = 0; e < E_EXP; e++) se += expf(acc[e] - m);
        float z = m + logf(se);

        int i1 = 0; float l1 = acc[0];
        #pragma unroll
        for (int e = 1; e < E_EXP; e++) if (acc[e] > l1) { l1 = acc[e]; i1 = e; }
        int i2 = -1; float l2 = -1e30f;
        #pragma unroll
        for (int e = 0; e < E_EXP; e++)
            if (e != i1 && acc[e] > l2) { l2 = acc[e]; i2 = e; }

        float q  = expf(l2 - l1);
        float c1 = 1.f / (1.f + q);
        float c2 = q / (1.f + q);

        if (lane == 0) {
            g_sel[2 * gwarp]     = i1;
            g_sel[2 * gwarp + 1] = i2;
            g_comb[2 * gwarp]     = c1;
            g_comb[2 * gwarp + 1] = c2;
            atomicAdd(&s_z2, z * z);
        }
        if (lane < E_EXP) atomicAdd(&s_p[lane], expf(acc[lane] - m) / se);
    }
    __syncthreads();
    if (threadIdx.x < E_EXP) atomicAdd(&g_sumprobs[threadIdx.x], s_p[threadIdx.x]);
    if (threadIdx.x == 0)    atomicAdd(&g_z2, s_z2);
}

// ---------------- ordered per-expert rank ----------------
__global__ void pos_kernel() {
    __shared__ int warpCnt[8][E_EXP];
    __shared__ int running[E_EXP];
    const int tid  = threadIdx.x;
    const int wid  = tid >> 5;
    const int lane = tid & 31;
    if (tid < E_EXP) running[tid] = 0;
    __syncthreads();

    const int base = blockIdx.x * SPB;
    for (int it = 0; it < SPB / 256; it++) {
        const int s = base + it * 256 + tid;
        const int e = g_sel[s];
        unsigned peers = __match_any_sync(0xffffffffu, e);
        const int rank = __popc(peers & ((1u << lane) - 1u));
        if (lane < E_EXP) warpCnt[wid][lane] = 0;
        __syncwarp();
        if (rank == 0) warpCnt[wid][e] = __popc(peers);
        __syncthreads();
        int off = running[e] + rank;
        for (int w = 0; w < wid; w++) off += warpCnt[w][e];
        g_poslocal[s] = off;
        __syncthreads();
        if (tid < E_EXP) {
            int tot = 0;
            #pragma unroll
            for (int w = 0; w < 8; w++) tot += warpCnt[w][tid];
            running[tid] += tot;
        }
        __syncthreads();
    }
    if (tid < E_EXP) g_blkCnt[blockIdx.x][tid] = running[tid];
}

__global__ void scan_kernel() {
    const int e = threadIdx.x;
    if (e >= E_EXP) return;
    int run = 0;
    for (int b = 0; b < NB; b++) {
        g_blkOff[b][e] = run;
        run += g_blkCnt[b][e];
    }
    g_cnt[e] = run;
}

// ---------------- scatter ----------------
__global__ void scatter_kernel(const float* __restrict__ x) {
    const int gwarp = (blockIdx.x * blockDim.x + threadIdx.x) >> 5;
    const int lane  = threadIdx.x & 31;
    if (gwarp >= TK_SLOTS) return;
    const int e   = g_sel[gwarp];
    const int pos = g_poslocal[gwarp] + g_blkOff[gwarp / SPB][e];
    int slot = -1;
    if (pos < CAP) {
        slot = e * CAP + pos;
        const float4* src = (const float4*)(x + (size_t)(gwarp >> 1) * D_DIM);
        float4* dst = (float4*)(g_expert_in + (size_t)slot * D_DIM);
        #pragma unroll
        for (int i = 0; i < 8; i++) dst[lane + 32 * i] = src[lane + 32 * i];
    }
    if (lane == 0) g_slot[gwarp] = slot;
}

// ---------------- weight transpose: dst[c][r] = src[r][c], per expert ----------------
__global__ void transpose_kernel(const float* __restrict__ src, float* __restrict__ dst,
                                 int R, int Cd) {
    __shared__ float tile[32][33];
    const size_t eoff = (size_t)blockIdx.z * R * Cd;
    const float* S = src + eoff;
    float* Dp = dst + eoff;
    const int c0 = blockIdx.x * 32, r0 = blockIdx.y * 32;
    const int tx = threadIdx.x, ty = threadIdx.y;
    #pragma unroll
    for (int i = 0; i < 32; i += 8)
        tile[ty + i][tx] = S[(size_t)(r0 + ty + i) * Cd + (c0 + tx)];
    __syncthreads();
    #pragma unroll
    for (int i = 0; i < 32; i += 8)
        Dp[(size_t)(c0 + ty + i) * R + (r0 + tx)] = tile[tx][ty + i];
}

// ---------------- tf32 mma.sync grouped GEMM ----------------
// C[m,n] = sum_k A[m,k] * Bt[n,k].  CTA tile 128x128, K-chunk 32.
// 8 warps: 2 (m) x 4 (n); warp tile 64x32; mma m16n8k8.
// SMEM stride 36 floats -> fragment loads hit all 32 banks.
#define SM_STRIDE 36

template <int Kdim, int Ndim, int WHICH>
__global__ __launch_bounds__(256)
void mma_gemm_kernel(const float* __restrict__ Wt) {
    const int e   = blockIdx.z;
    const int cnt = g_cnt[e];
    const int m0  = blockIdx.y * 128;
    if (m0 >= cnt) return;
    const int n0  = blockIdx.x * 128;

    const float* __restrict__ Abase = (WHICH == 1) ? g_expert_in : g_act;
    float*       __restrict__ Cbase = (WHICH == 1) ? g_h : g_eout;
    const float* __restrict__ A = Abase + (size_t)e * CAP * Kdim + (size_t)m0 * Kdim;
    const float* __restrict__ B = Wt + (size_t)e * Ndim * Kdim + (size_t)n0 * Kdim;
    float*       __restrict__ C = Cbase + (size_t)e * CAP * Ndim + (size_t)m0 * Ndim + n0;

    __shared__ float As[128 * SM_STRIDE];
    __shared__ float Bs[128 * SM_STRIDE];

    const int tid  = threadIdx.x;
    const int lane = tid & 31;
    const int wid  = tid >> 5;
    const int warp_m = (wid >> 2) * 64;   // 0 or 64
    const int warp_n = (wid & 3) * 32;    // 0,32,64,96
    const int g  = lane >> 2;             // 0..7
    const int t4 = lane & 3;              // 0..3

    const int lrow = tid >> 3;            // 0..31
    const int lc4  = (tid & 7) * 4;       // 0..28

    float acc[4][4][4];
    #pragma unroll
    for (int i = 0; i < 4; i++)
        #pragma unroll
        for (int j = 0; j < 4; j++)
            #pragma unroll
            for (int q = 0; q < 4; q++) acc[i][j][q] = 0.f;

    float4 ra[4], rb[4];
    const int NC = Kdim / 32;

    // prologue: load chunk 0
    #pragma unroll
    for (int i = 0; i < 4; i++) {
        ra[i] = *(const float4*)(A + (size_t)(lrow + 32 * i) * Kdim + lc4);
        rb[i] = *(const float4*)(B + (size_t)(lrow + 32 * i) * Kdim + lc4);
    }
    #pragma unroll
    for (int i = 0; i < 4; i++) {
        float4 va = ra[i], vb = rb[i];
        float* pa = &As[(lrow + 32 * i) * SM_STRIDE + lc4];
        float* pb = &Bs[(lrow + 32 * i) * SM_STRIDE + lc4];
        pa[0] = __uint_as_float(f2tf32(va.x)); pa[1] = __uint_as_float(f2tf32(va.y));
        pa[2] = __uint_as_float(f2tf32(va.z)); pa[3] = __uint_as_float(f2tf32(va.w));
        pb[0] = __uint_as_float(f2tf32(vb.x)); pb[1] = __uint_as_float(f2tf32(vb.y));
        pb[2] = __uint_as_float(f2tf32(vb.z)); pb[3] = __uint_as_float(f2tf32(vb.w));
    }
    __syncthreads();

    for (int c = 0; c < NC; c++) {
        // prefetch next chunk to registers (overlaps with mma below)
        if (c + 1 < NC) {
            const int k0 = (c + 1) * 32;
            #pragma unroll
            for (int i = 0; i < 4; i++) {
                ra[i] = *(const float4*)(A + (size_t)(lrow + 32 * i) * Kdim + k0 + lc4);
                rb[i] = *(const float4*)(B + (size_t)(lrow + 32 * i) * Kdim + k0 + lc4);
            }
        }
        // mma over current chunk
        #pragma unroll
        for (int ks = 0; ks < 4; ks++) {
            uint32_t bf[4][2];
            #pragma unroll
            for (int nf = 0; nf < 4; nf++) {
                const int n = warp_n + nf * 8 + g;
                bf[nf][0] = __float_as_uint(Bs[n * SM_STRIDE + ks * 8 + t4]);
                bf[nf][1] = __float_as_uint(Bs[n * SM_STRIDE + ks * 8 + 4 + t4]);
            }
            #pragma unroll
            for (int mf = 0; mf < 4; mf++) {
                const int m = warp_m + mf * 16 + g;
                const uint32_t a0 = __float_as_uint(As[m * SM_STRIDE + ks * 8 + t4]);
                const uint32_t a1 = __float_as_uint(As[(m + 8) * SM_STRIDE + ks * 8 + t4]);
                const uint32_t a2 = __float_as_uint(As[m * SM_STRIDE + ks * 8 + 4 + t4]);
                const uint32_t a3 = __float_as_uint(As[(m + 8) * SM_STRIDE + ks * 8 + 4 + t4]);
                #pragma unroll
                for (int nf = 0; nf < 4; nf++)
                    mma_tf32(acc[mf][nf], a0, a1, a2, a3, bf[nf][0], bf[nf][1]);
            }
        }
        __syncthreads();
        if (c + 1 < NC) {
            #pragma unroll
            for (int i = 0; i < 4; i++) {
                float4 va = ra[i], vb = rb[i];
                float* pa = &As[(lrow + 32 * i) * SM_STRIDE + lc4];
                float* pb = &Bs[(lrow + 32 * i) * SM_STRIDE + lc4];
                pa[0] = __uint_as_float(f2tf32(va.x)); pa[1] = __uint_as_float(f2tf32(va.y));
                pa[2] = __uint_as_float(f2tf32(va.z)); pa[3] = __uint_as_float(f2tf32(va.w));
                pb[0] = __uint_as_float(f2tf32(vb.x)); pb[1] = __uint_as_float(f2tf32(vb.y));
                pb[2] = __uint_as_float(f2tf32(vb.z)); pb[3] = __uint_as_float(f2tf32(vb.w));
            }
            __syncthreads();
        }
    }

    // epilogue
    #pragma unroll
    for (int mf = 0; mf < 4; mf++) {
        const int row = warp_m + mf * 16 + g;
        #pragma unroll
        for (int nf = 0; nf < 4; nf++) {
            const int col = warp_n + nf * 8 + t4 * 2;
            *(float2*)(C + (size_t)row * Ndim + col) =
                make_float2(acc[mf][nf][0], acc[mf][nf][1]);
            *(float2*)(C + (size_t)(row + 8) * Ndim + col) =
                make_float2(acc[mf][nf][2], acc[mf][nf][3]);
        }
    }
}

// ---------------- SiLU(gate)*up ----------------
__global__ void silu_kernel() {
    const int row = blockIdx.x;
    const int e = row / CAP;
    if ((row - e * CAP) >= g_cnt[e]) return;
    const float4* h = (const float4*)(g_h + (size_t)row * TWO_I);
    float4* a = (float4*)(g_act + (size_t)row * I_DIM);
    for (int i = threadIdx.x; i < I_DIM / 4; i += blockDim.x) {
        float4 g = h[i];
        float4 u = h[I_DIM / 4 + i];
        float4 o;
        o.x = g.x / (1.f + expf(-g.x)) * u.x;
        o.y = g.y / (1.f + expf(-g.y)) * u.y;
        o.z = g.z / (1.f + expf(-g.z)) * u.z;
        o.w = g.w / (1.f + expf(-g.w)) * u.w;
        a[i] = o;
    }
}

// ---------------- gather + combine ----------------
__global__ void gather_kernel(float* __restrict__ out) {
    const int t    = (blockIdx.x * blockDim.x + threadIdx.x) >> 5;
    const int lane = threadIdx.x & 31;
    if (t >= T_TOK) return;
    const int s0 = 2 * t, s1 = s0 + 1;
    const int sl0 = g_slot[s0], sl1 = g_slot[s1];
    const float w0 = g_comb[s0], w1 = g_comb[s1];
    const float4* r0 = (sl0 >= 0) ? (const float4*)(g_eout + (size_t)sl0 * D_DIM) : nullptr;
    const float4* r1 = (sl1 >= 0) ? (const float4*)(g_eout + (size_t)sl1 * D_DIM) : nullptr;
    float4* orow = (float4*)(out + (size_t)t * D_DIM);
    #pragma unroll
    for (int ii = 0; ii < 8; ii++) {
        const int i = lane + 32 * ii;
        float4 a = make_float4(0.f, 0.f, 0.f, 0.f);
        if (r0) { float4 v = r0[i]; a.x += w0 * v.x; a.y += w0 * v.y; a.z += w0 * v.z; a.w += w0 * v.w; }
        if (r1) { float4 v = r1[i]; a.x += w1 * v.x; a.y += w1 * v.y; a.z += w1 * v.z; a.w += w1 * v.w; }
        orow[i] = a;
    }
}

// ---------------- final scalars ----------------
__global__ void finalize_kernel(float* __restrict__ out) {
    __shared__ float cnts[E_EXP];
    const size_t base = (size_t)T_TOK * D_DIM;
    if (threadIdx.x < E_EXP) {
        float c = (float)g_cnt[threadIdx.x];
        cnts[threadIdx.x] = c;
        out[base + threadIdx.x] = c;
    }
    __syncthreads();
    if (threadIdx.x == 0) {
        float total = 0.f;
        #pragma unroll
        for (int e = 0; e < E_EXP; e++) total += cnts[e];
        total = fmaxf(total, 1.f);
        float ent = 0.f, lb = 0.f;
        #pragma unroll
        for (int e = 0; e < E_EXP; e++) {
            float f = cnts[e] / total;
            ent -= f * logf(f + 1e-6f);
            lb  += (f * 2.0f) * (g_sumprobs[e] / (float)T_TOK);
        }
        lb *= (float)E_EXP;
        out[base + 16] = ent;
        out[base + 17] = lb;
        out[base + 18] = g_z2 / (float)T_TOK;
    }
}

// ---------------- launch ----------------
extern "C" void kernel_launch(void* const* d_in, const int* in_sizes, int n_in,
                              void* d_out, int out_size) {
    const float* x      = (const float*)d_in[0];
    const float* router = (const float*)d_in[1];
    const float* w_ug   = (const float*)d_in[2];
    const float* w_dn   = (const float*)d_in[3];
    float* out = (float*)d_out;

    float *wug_t = nullptr, *wdn_t = nullptr;
    cudaGetSymbolAddress((void**)&wug_t, g_wug_t);
    cudaGetSymbolAddress((void**)&wdn_t, g_wdn_t);

    // weight transposes (independent of routing)
    transpose_kernel<<<dim3(TWO_I / 32, D_DIM / 32, E_EXP), dim3(32, 8)>>>(w_ug, wug_t, D_DIM, TWO_I);
    transpose_kernel<<<dim3(D_DIM / 32, I_DIM / 32, E_EXP), dim3(32, 8)>>>(w_dn, wdn_t, I_DIM, D_DIM);

    zero_stats_kernel<<<1, 32>>>();
    router_kernel<<<T_TOK / 8, 256>>>(x, router);
    pos_kernel<<<NB, 256>>>();
    scan_kernel<<<1, 32>>>();
    scatter_kernel<<<TK_SLOTS / 8, 256>>>(x);

    mma_gemm_kernel<D_DIM, TWO_I, 1>
        <<<dim3(TWO_I / 128, CAP / 128, E_EXP), 256>>>(wug_t);
    silu_kernel<<<E_EXP * CAP, 256>>>();
    mma_gemm_kernel<I_DIM, D_DIM, 2>
        <<<dim3(D_DIM / 128, CAP / 128, E_EXP), 256>>>(wdn_t);

    gather_kernel<<<T_TOK / 8, 256>>>(out);
    finalize_kernel<<<1, 32>>>(out);
}